// round 6
// baseline (speedup 1.0000x reference)
#include <cuda_runtime.h>
#include <cuda_bf16.h>
#include <cstdint>

#define NN 100000
#define EE 3200000
#define DINF 256
#define DHID 256
#define DO 64
#define KHOPS 10
#define NB_SCAN 98   // ceil(100000/1024)

// ---------------- scratch (device globals; no allocation allowed) -------------
__device__ __align__(16) float g_hidden[(size_t)NN * DHID];           // 102.4 MB
__device__ __align__(16) float g_h[(size_t)(KHOPS + 1) * NN * DO];    // 281.6 MB
__device__ float g_dinv[NN];
__device__ int   g_deg[NN];
__device__ int   g_cursor[NN];
__device__ int   g_off[NN + 1];
__device__ int2  g_csr[EE];                                           // {src, bitcast(norm)}
__device__ int   g_bsum[NB_SCAN];
__device__ int   g_is64;

// ---------------- edge dtype helpers ------------------------------------------
__device__ __forceinline__ int edge_at(const void* eiv, long long idx) {
    int v;
    if (g_is64) v = (int)((const long long*)eiv)[idx];
    else        v = ((const int*)eiv)[idx];
    return min(max(v, 0), NN - 1);
}

// ---------------- init + dtype detect (fused) ----------------------------------
// int64 little-endian node ids (< 2^31) have all-zero odd 32-bit words;
// int32 ids in [0,100000) are nonzero with prob ~1-1e-5 per word.
__global__ void k_initdet(const int* __restrict__ w) {
    int i = blockIdx.x * blockDim.x + threadIdx.x;
    if (i < NN) { g_deg[i] = 1; g_cursor[i] = 0; }
    if (blockIdx.x == 391) {   // this block's indices are >= NN: free for detection
        __shared__ int nz;
        if (threadIdx.x == 0) nz = 0;
        __syncthreads();
        int local = 0;
        for (int j = threadIdx.x; j < 2048; j += 256)
            if (w[2 * j + 1] != 0) local = 1;
        if (local) atomicAdd(&nz, 1);
        __syncthreads();
        if (threadIdx.x == 0) g_is64 = (nz == 0) ? 1 : 0;
    }
}

__global__ void k_count(const void* __restrict__ eiv) {
    int e = blockIdx.x * blockDim.x + threadIdx.x;
    if (e < EE) atomicAdd(&g_deg[edge_at(eiv, (long long)EE + e)], 1);
}

// ---------------- scanA (+dinv): block-local exclusive scan of deg-1 ----------
__global__ void k_scanA() {
    int tid = threadIdx.x;
    int i = blockIdx.x * 1024 + tid;
    int v = 0;
    if (i < NN) {
        int d = g_deg[i];
        v = d - 1;
        g_dinv[i] = rsqrtf((float)d);
    }
    int lane = tid & 31, wid = tid >> 5;
    int x = v;
    #pragma unroll
    for (int o = 1; o < 32; o <<= 1) {
        int t = __shfl_up_sync(0xffffffffu, x, o);
        if (lane >= o) x += t;
    }
    __shared__ int wsum[32];
    if (lane == 31) wsum[wid] = x;
    __syncthreads();
    if (wid == 0) {
        int y = wsum[lane];
        #pragma unroll
        for (int o = 1; o < 32; o <<= 1) {
            int t = __shfl_up_sync(0xffffffffu, y, o);
            if (lane >= o) y += t;
        }
        wsum[lane] = y;
    }
    __syncthreads();
    int incl = x + (wid > 0 ? wsum[wid - 1] : 0);
    if (i < NN) g_off[i] = incl - v;
    if (tid == 1023) g_bsum[blockIdx.x] = incl;
}

// ---------------- scanC: add cross-block prefix --------------------------------
__global__ void k_scanC() {
    __shared__ int pre;
    if (threadIdx.x == 0) {
        int s = 0;
        for (int b = 0; b < blockIdx.x; b++) s += g_bsum[b];
        pre = s;
    }
    __syncthreads();
    int i = blockIdx.x * 1024 + threadIdx.x;
    if (i < NN) g_off[i] += pre;
    if (i == 0) g_off[NN] = EE;
}

// ---------------- CSR fill ----------------------------------------------------
__global__ void k_fill(const void* __restrict__ eiv) {
    int e = blockIdx.x * blockDim.x + threadIdx.x;
    if (e < EE) {
        int r = edge_at(eiv, e);
        int c = edge_at(eiv, (long long)EE + e);
        float w = g_dinv[r] * g_dinv[c];
        int p = g_off[c] + atomicAdd(&g_cursor[c], 1);
        if (p < EE) g_csr[p] = make_int2(r, __float_as_int(w));
    }
}

// ================= split-bf16 mma.sync GEMM ====================================
// C[M=1e5, NCT] = A[M,256] @ W[256,NCT] + bias, optional relu.
// 3-pass Markidis split: hi*hi + lo*hi + hi*lo, fp32 accumulation.
// mma.sync m16n8k16 bf16 (baseline PTX, works on compute_103 target).
__device__ __forceinline__ void split1(float x, __nv_bfloat16& h, __nv_bfloat16& l) {
    h = __float2bfloat16_rn(x);
    l = __float2bfloat16_rn(x - __bfloat162float(h));
}
__device__ __forceinline__ void split_pack(float a, float b, uint32_t& hi, uint32_t& lo) {
    __nv_bfloat16 ah, al, bh, bl;
    split1(a, ah, al); split1(b, bh, bl);
    __nv_bfloat162 h2; h2.x = ah; h2.y = bh;
    __nv_bfloat162 l2; l2.x = al; l2.y = bl;
    hi = *(uint32_t*)&h2;
    lo = *(uint32_t*)&l2;
}
__device__ __forceinline__ void mma16816(float* d, const uint32_t* a, const uint32_t* b) {
    asm volatile(
        "mma.sync.aligned.m16n8k16.row.col.f32.bf16.bf16.f32 "
        "{%0,%1,%2,%3}, {%4,%5,%6,%7}, {%8,%9}, {%0,%1,%2,%3};"
        : "+f"(d[0]), "+f"(d[1]), "+f"(d[2]), "+f"(d[3])
        : "r"(a[0]), "r"(a[1]), "r"(a[2]), "r"(a[3]), "r"(b[0]), "r"(b[1]));
}

// BM=64 fixed, BK=32 fixed, warp tile 32x32. T threads = (BN/32)*2 warps * 32.
#define KPAD 40   // smem k-stride in bf16 elems (conflict-free for frag loads)
template<int BN, int T, bool RELU, bool FIRST>
__global__ void __launch_bounds__(T) k_gemm_mma(
    const float* __restrict__ Ain, const float* __restrict__ W,
    const float* __restrict__ bias) {
    const int NCT = FIRST ? DHID : DO;
    const float* __restrict__ A = FIRST ? Ain : g_hidden;
    float* __restrict__ C = FIRST ? g_hidden : g_h;
    const int WCOLS = BN / 32;

    __shared__ __nv_bfloat16 Ahi[64 * KPAD], Alo[64 * KPAD];
    __shared__ __nv_bfloat16 Bhi[BN * KPAD], Blo[BN * KPAD];

    int tid = threadIdx.x;
    int wid = tid >> 5, lane = tid & 31;
    int wrow = wid / WCOLS, wcol = wid % WCOLS;
    int mBase = blockIdx.x * 64;
    int nBase = blockIdx.y * BN;
    int r = lane >> 2, c2 = (lane & 3) * 2;

    float acc[2][4][4];
    #pragma unroll
    for (int i = 0; i < 2; i++)
        #pragma unroll
        for (int j = 0; j < 4; j++)
            #pragma unroll
            for (int q = 0; q < 4; q++) acc[i][j][q] = 0.f;

    for (int k0 = 0; k0 < 256; k0 += 32) {
        // ---- A tile 64x32 fp32 -> split bf16 smem ----
        #pragma unroll
        for (int q = 0; q < 512 / T; q++) {
            int L = tid + q * T;
            int row = L >> 3, f4 = L & 7;
            int rowG = min(mBase + row, NN - 1);
            float4 v = __ldg((const float4*)(A + (size_t)rowG * 256 + k0 + f4 * 4));
            int idx = row * KPAD + f4 * 4;
            uint32_t h01, l01, h23, l23;
            split_pack(v.x, v.y, h01, l01);
            split_pack(v.z, v.w, h23, l23);
            *(uint32_t*)&Ahi[idx] = h01;     *(uint32_t*)&Ahi[idx + 2] = h23;
            *(uint32_t*)&Alo[idx] = l01;     *(uint32_t*)&Alo[idx + 2] = l23;
        }
        // ---- B tile 32xBN fp32 -> split bf16 smem [n][k] ----
        #pragma unroll
        for (int q = 0; q < (32 * BN / 4) / T; q++) {
            int L = tid + q * T;
            int k = L / (BN / 4), f4 = L % (BN / 4);
            float4 v = __ldg((const float4*)(W + (size_t)(k0 + k) * NCT + nBase + f4 * 4));
            int n = f4 * 4;
            __nv_bfloat16 h, l;
            split1(v.x, h, l); Bhi[(n + 0) * KPAD + k] = h; Blo[(n + 0) * KPAD + k] = l;
            split1(v.y, h, l); Bhi[(n + 1) * KPAD + k] = h; Blo[(n + 1) * KPAD + k] = l;
            split1(v.z, h, l); Bhi[(n + 2) * KPAD + k] = h; Blo[(n + 2) * KPAD + k] = l;
            split1(v.w, h, l); Bhi[(n + 3) * KPAD + k] = h; Blo[(n + 3) * KPAD + k] = l;
        }
        __syncthreads();

        #pragma unroll
        for (int kk = 0; kk < 32; kk += 16) {
            uint32_t ah[2][4], al[2][4];
            #pragma unroll
            for (int mt = 0; mt < 2; mt++) {
                int m = wrow * 32 + mt * 16 + r;
                int o0 = m * KPAD + kk + c2;
                int o1 = (m + 8) * KPAD + kk + c2;
                ah[mt][0] = *(uint32_t*)&Ahi[o0];
                ah[mt][1] = *(uint32_t*)&Ahi[o1];
                ah[mt][2] = *(uint32_t*)&Ahi[o0 + 8];
                ah[mt][3] = *(uint32_t*)&Ahi[o1 + 8];
                al[mt][0] = *(uint32_t*)&Alo[o0];
                al[mt][1] = *(uint32_t*)&Alo[o1];
                al[mt][2] = *(uint32_t*)&Alo[o0 + 8];
                al[mt][3] = *(uint32_t*)&Alo[o1 + 8];
            }
            #pragma unroll
            for (int nt = 0; nt < 4; nt++) {
                int n = wcol * 32 + nt * 8 + r;
                int o = n * KPAD + kk + c2;
                uint32_t bh[2], bl[2];
                bh[0] = *(uint32_t*)&Bhi[o];
                bh[1] = *(uint32_t*)&Bhi[o + 8];
                bl[0] = *(uint32_t*)&Blo[o];
                bl[1] = *(uint32_t*)&Blo[o + 8];
                #pragma unroll
                for (int mt = 0; mt < 2; mt++) {
                    mma16816(acc[mt][nt], ah[mt], bh);
                    mma16816(acc[mt][nt], al[mt], bh);
                    mma16816(acc[mt][nt], ah[mt], bl);
                }
            }
        }
        __syncthreads();
    }

    // ---- epilogue: bias + relu, direct gmem stores ----
    #pragma unroll
    for (int nt = 0; nt < 4; nt++) {
        int gc = nBase + wcol * 32 + nt * 8 + c2;
        float bx = __ldg(&bias[gc]), by = __ldg(&bias[gc + 1]);
        #pragma unroll
        for (int mt = 0; mt < 2; mt++) {
            int gr = mBase + wrow * 32 + mt * 16 + r;
            float2 o0, o1;
            o0.x = acc[mt][nt][0] + bx; o0.y = acc[mt][nt][1] + by;
            o1.x = acc[mt][nt][2] + bx; o1.y = acc[mt][nt][3] + by;
            if (RELU) {
                o0.x = fmaxf(o0.x, 0.f); o0.y = fmaxf(o0.y, 0.f);
                o1.x = fmaxf(o1.x, 0.f); o1.y = fmaxf(o1.y, 0.f);
            }
            if (gr < NN)     *(float2*)(C + (size_t)gr * NCT + gc) = o0;
            if (gr + 8 < NN) *(float2*)(C + (size_t)(gr + 8) * NCT + gc) = o1;
        }
    }
}

// ---------------- propagation hop: gather over dest-CSR ----------------------
__global__ void __launch_bounds__(256) k_hop(int hop) {
    int gw = (blockIdx.x * blockDim.x + threadIdx.x) >> 5;
    if (gw >= NN) return;
    int lane = threadIdx.x & 31;
    int hf = lane >> 4, sub = lane & 15;
    const float4* __restrict__ hprev = (const float4*)(g_h + (size_t)hop * NN * DO);
    float4* __restrict__ hnew = (float4*)(g_h + (size_t)(hop + 1) * NN * DO);
    int start = g_off[gw], end = g_off[gw + 1];

    float ax = 0.f, ay = 0.f, az = 0.f, aw = 0.f;
    for (int base = start; base < end; base += 32) {
        int i = base + lane;
        int2 meta = make_int2(0, 0);
        if (i < end) meta = g_csr[i];
        int lim = end - base; if (lim > 32) lim = 32;
        for (int j2 = 0; j2 < lim; j2 += 2) {
            int j = (j2 + hf) & 31;
            int s = __shfl_sync(0xffffffffu, meta.x, j);
            float w = __int_as_float(__shfl_sync(0xffffffffu, meta.y, j));
            float4 v = __ldg(&hprev[s * 16 + sub]);
            ax = fmaf(w, v.x, ax); ay = fmaf(w, v.y, ay);
            az = fmaf(w, v.z, az); aw = fmaf(w, v.w, aw);
        }
    }
    ax += __shfl_xor_sync(0xffffffffu, ax, 16);
    ay += __shfl_xor_sync(0xffffffffu, ay, 16);
    az += __shfl_xor_sync(0xffffffffu, az, 16);
    aw += __shfl_xor_sync(0xffffffffu, aw, 16);
    if (hf == 0) {
        float d = g_dinv[gw];
        float w = d * d;
        float4 v = __ldg(&hprev[gw * 16 + sub]);
        hnew[gw * 16 + sub] = make_float4(fmaf(w, v.x, ax), fmaf(w, v.y, ay),
                                          fmaf(w, v.z, az), fmaf(w, v.w, aw));
    }
}

// ---------------- adaptive hop pooling epilogue ------------------------------
__global__ void __launch_bounds__(256) k_pool(const float* __restrict__ pw,
                                              const float* __restrict__ pb,
                                              float* __restrict__ out) {
    int gw = (blockIdx.x * blockDim.x + threadIdx.x) >> 5;
    if (gw >= NN) return;
    int lane = threadIdx.x & 31;
    float2 w2 = ((const float2*)pw)[lane];
    float bias = pb[0];
    float ox = 0.f, oy = 0.f;
    #pragma unroll
    for (int k = 0; k <= KHOPS; k++) {
        const float2* hp = (const float2*)(g_h + (size_t)k * NN * DO + (size_t)gw * DO);
        float2 v = __ldg(&hp[lane]);
        float p = v.x * w2.x + v.y * w2.y;
        #pragma unroll
        for (int o = 16; o; o >>= 1) p += __shfl_xor_sync(0xffffffffu, p, o);
        float sc = 1.f / (1.f + expf(-(p + bias)));
        ox = fmaf(sc, v.x, ox);
        oy = fmaf(sc, v.y, oy);
    }
    ((float2*)(out + (size_t)gw * DO))[lane] = make_float2(ox, oy);
}

// ---------------- launch -----------------------------------------------------
extern "C" void kernel_launch(void* const* d_in, const int* in_sizes, int n_in,
                              void* d_out, int out_size) {
    const float* x  = (const float*)d_in[0];
    const void*  ei = d_in[1];
    const float* W1 = (const float*)d_in[2];
    const float* b1 = (const float*)d_in[3];
    const float* W2 = (const float*)d_in[4];
    const float* b2 = (const float*)d_in[5];
    const float* pw = (const float*)d_in[6];
    const float* pb = (const float*)d_in[7];
    float* out = (float*)d_out;

    k_initdet<<<392, 256>>>((const int*)ei);                             // #0
    k_count  <<<(EE + 255) / 256, 256>>>(ei);                            // #1
    k_scanA  <<<NB_SCAN, 1024>>>();                                      // #2 (+dinv)
    k_gemm_mma<128, 256, true,  true ><<<dim3(1563, 2), 256>>>(x, W1, b1);        // #3 (profiled)
    k_scanC  <<<NB_SCAN, 1024>>>();                                      // #4
    k_fill   <<<(EE + 255) / 256, 256>>>(ei);                            // #5
    k_gemm_mma<64,  128, false, false><<<dim3(1563, 1), 128>>>(nullptr, W2, b2);  // #6

    for (int k = 0; k < KHOPS; k++)                                      // #7..16
        k_hop<<<NN / 8, 256>>>(k);

    k_pool<<<NN / 8, 256>>>(pw, pb, out);                                // #17
}

// round 8
// speedup vs baseline: 1.2714x; 1.2714x over previous
#include <cuda_runtime.h>
#include <cuda_bf16.h>
#include <cstdint>

#define NN 100000
#define EE 3200000
#define DINF 256
#define DHID 256
#define DO 64
#define KHOPS 10
#define NB_SCAN 98   // ceil(100000/1024)

// ---------------- scratch (device globals; no allocation allowed) -------------
__device__ __align__(16) float g_hidden[(size_t)NN * DHID];           // 102.4 MB
__device__ __align__(16) float g_h[(size_t)(KHOPS + 1) * NN * DO];    // 281.6 MB
__device__ float g_dinv[NN];
__device__ int   g_deg[NN];
__device__ int   g_cursor[NN];
__device__ int   g_off[NN + 1];
__device__ int2  g_csr[EE];                                           // {src, bitcast(norm)}
__device__ int   g_bsum[NB_SCAN];
__device__ int   g_is64;

// ---------------- edge dtype helpers ------------------------------------------
__device__ __forceinline__ int edge_at(const void* eiv, long long idx) {
    int v;
    if (g_is64) v = (int)((const long long*)eiv)[idx];
    else        v = ((const int*)eiv)[idx];
    return min(max(v, 0), NN - 1);
}

// ---------------- init + dtype detect (fused) ----------------------------------
__global__ void k_initdet(const int* __restrict__ w) {
    int i = blockIdx.x * blockDim.x + threadIdx.x;
    if (i < NN) { g_deg[i] = 1; g_cursor[i] = 0; }
    if (blockIdx.x == 391) {   // this block's indices are >= NN: free for detection
        __shared__ int nz;
        if (threadIdx.x == 0) nz = 0;
        __syncthreads();
        int local = 0;
        for (int j = threadIdx.x; j < 2048; j += 256)
            if (w[2 * j + 1] != 0) local = 1;
        if (local) atomicAdd(&nz, 1);
        __syncthreads();
        if (threadIdx.x == 0) g_is64 = (nz == 0) ? 1 : 0;
    }
}

__global__ void k_count(const void* __restrict__ eiv) {
    int e = blockIdx.x * blockDim.x + threadIdx.x;
    if (e < EE) atomicAdd(&g_deg[edge_at(eiv, (long long)EE + e)], 1);
}

// ---------------- scanA (+dinv): block-local exclusive scan of deg-1 ----------
__global__ void k_scanA() {
    int tid = threadIdx.x;
    int i = blockIdx.x * 1024 + tid;
    int v = 0;
    if (i < NN) {
        int d = g_deg[i];
        v = d - 1;
        g_dinv[i] = rsqrtf((float)d);
    }
    int lane = tid & 31, wid = tid >> 5;
    int x = v;
    #pragma unroll
    for (int o = 1; o < 32; o <<= 1) {
        int t = __shfl_up_sync(0xffffffffu, x, o);
        if (lane >= o) x += t;
    }
    __shared__ int wsum[32];
    if (lane == 31) wsum[wid] = x;
    __syncthreads();
    if (wid == 0) {
        int y = wsum[lane];
        #pragma unroll
        for (int o = 1; o < 32; o <<= 1) {
            int t = __shfl_up_sync(0xffffffffu, y, o);
            if (lane >= o) y += t;
        }
        wsum[lane] = y;
    }
    __syncthreads();
    int incl = x + (wid > 0 ? wsum[wid - 1] : 0);
    if (i < NN) g_off[i] = incl - v;
    if (tid == 1023) g_bsum[blockIdx.x] = incl;
}

// ---------------- scanC: add cross-block prefix --------------------------------
__global__ void k_scanC() {
    __shared__ int pre;
    if (threadIdx.x == 0) {
        int s = 0;
        for (int b = 0; b < blockIdx.x; b++) s += g_bsum[b];
        pre = s;
    }
    __syncthreads();
    int i = blockIdx.x * 1024 + threadIdx.x;
    if (i < NN) g_off[i] += pre;
    if (i == 0) g_off[NN] = EE;
}

// ---------------- CSR fill ----------------------------------------------------
__global__ void k_fill(const void* __restrict__ eiv) {
    int e = blockIdx.x * blockDim.x + threadIdx.x;
    if (e < EE) {
        int r = edge_at(eiv, e);
        int c = edge_at(eiv, (long long)EE + e);
        float w = g_dinv[r] * g_dinv[c];
        int p = g_off[c] + atomicAdd(&g_cursor[c], 1);
        if (p < EE) g_csr[p] = make_int2(r, __float_as_int(w));
    }
}

// ================= split-bf16 mma.sync GEMM ====================================
// C[M=1e5, NCT] = A[M,256] @ W[256,NCT] + bias, optional relu.
// 3-pass Markidis split: hi*hi + lo*hi + hi*lo, fp32 accumulation.
// A smem: bf16 [row][k] stride KPAD=40 (conflict-free frag loads).
// B smem: packed uint32 k-pairs [n][k2] stride 20 words (conflict-free frag
// loads, 4-way fill stores — fixes the 16-way conflict found in R6 ncu).
__device__ __forceinline__ void split1(float x, __nv_bfloat16& h, __nv_bfloat16& l) {
    h = __float2bfloat16_rn(x);
    l = __float2bfloat16_rn(x - __bfloat162float(h));
}
__device__ __forceinline__ void split_pack(float a, float b, uint32_t& hi, uint32_t& lo) {
    __nv_bfloat16 ah, al, bh, bl;
    split1(a, ah, al); split1(b, bh, bl);
    __nv_bfloat162 h2; h2.x = ah; h2.y = bh;
    __nv_bfloat162 l2; l2.x = al; l2.y = bl;
    hi = *(uint32_t*)&h2;
    lo = *(uint32_t*)&l2;
}
__device__ __forceinline__ void mma16816(float* d, const uint32_t* a, const uint32_t* b) {
    asm volatile(
        "mma.sync.aligned.m16n8k16.row.col.f32.bf16.bf16.f32 "
        "{%0,%1,%2,%3}, {%4,%5,%6,%7}, {%8,%9}, {%0,%1,%2,%3};"
        : "+f"(d[0]), "+f"(d[1]), "+f"(d[2]), "+f"(d[3])
        : "r"(a[0]), "r"(a[1]), "r"(a[2]), "r"(a[3]), "r"(b[0]), "r"(b[1]));
}

#define KPAD 40    // A smem k-stride in bf16 elems
#define BW 20      // B smem n-stride in uint32 (16 k-pairs + 4 pad)
template<int BN, int T, bool RELU, bool FIRST>
__global__ void __launch_bounds__(T) k_gemm_mma(
    const float* __restrict__ Ain, const float* __restrict__ W,
    const float* __restrict__ bias) {
    const int NCT = FIRST ? DHID : DO;
    const float* __restrict__ A = FIRST ? Ain : g_hidden;
    float* __restrict__ C = FIRST ? g_hidden : g_h;
    const int WCOLS = BN / 32;

    __shared__ __align__(16) __nv_bfloat16 Ahi[64 * KPAD], Alo[64 * KPAD];
    __shared__ uint32_t Bhi32[BN * BW], Blo32[BN * BW];

    int tid = threadIdx.x;
    int wid = tid >> 5, lane = tid & 31;
    int wrow = wid / WCOLS, wcol = wid % WCOLS;
    int mBase = blockIdx.x * 64;
    int nBase = blockIdx.y * BN;
    int r = lane >> 2, q = lane & 3, c2 = q * 2;

    float acc[2][4][4];
    #pragma unroll
    for (int i = 0; i < 2; i++)
        #pragma unroll
        for (int j = 0; j < 4; j++)
            #pragma unroll
            for (int p = 0; p < 4; p++) acc[i][j][p] = 0.f;

    // B-fill thread mapping: one n per thread (lane-consecutive), k-slice by tid/BN
    int bn = tid & (BN - 1);
    int bkBase = (tid / BN) * 16;     // T/BN == 2 slices of 16 k each

    for (int k0 = 0; k0 < 256; k0 += 32) {
        // ---- A tile 64x32 fp32 -> split bf16 smem (STS.64, ~2-way) ----
        #pragma unroll
        for (int it = 0; it < 512 / T; it++) {
            int L = tid + it * T;
            int row = L >> 3, f4 = L & 7;
            int rowG = min(mBase + row, NN - 1);
            float4 v = __ldg((const float4*)(A + (size_t)rowG * 256 + k0 + f4 * 4));
            int idx = row * KPAD + f4 * 4;
            uint32_t h01, l01, h23, l23;
            split_pack(v.x, v.y, h01, l01);
            split_pack(v.z, v.w, h23, l23);
            uint2 hh; hh.x = h01; hh.y = h23;
            uint2 ll; ll.x = l01; ll.y = l23;
            *(uint2*)&Ahi[idx] = hh;
            *(uint2*)&Alo[idx] = ll;
        }
        // ---- B tile 32xBN -> packed k-pair smem [n][k2] (4-way stores) ----
        #pragma unroll
        for (int i = 0; i < 8; i++) {
            int k = bkBase + i * 2;
            float w0 = __ldg(&W[(size_t)(k0 + k) * NCT + nBase + bn]);
            float w1 = __ldg(&W[(size_t)(k0 + k + 1) * NCT + nBase + bn]);
            __nv_bfloat16 h0, l0, h1, l1;
            split1(w0, h0, l0);
            split1(w1, h1, l1);
            __nv_bfloat162 hp; hp.x = h0; hp.y = h1;
            __nv_bfloat162 lp; lp.x = l0; lp.y = l1;
            Bhi32[bn * BW + (k >> 1)] = *(uint32_t*)&hp;
            Blo32[bn * BW + (k >> 1)] = *(uint32_t*)&lp;
        }
        __syncthreads();

        #pragma unroll
        for (int kk = 0; kk < 32; kk += 16) {
            uint32_t ah[2][4], al[2][4];
            #pragma unroll
            for (int mt = 0; mt < 2; mt++) {
                int m = wrow * 32 + mt * 16 + r;
                int o0 = m * KPAD + kk + c2;
                int o1 = (m + 8) * KPAD + kk + c2;
                ah[mt][0] = *(uint32_t*)&Ahi[o0];
                ah[mt][1] = *(uint32_t*)&Ahi[o1];
                ah[mt][2] = *(uint32_t*)&Ahi[o0 + 8];
                ah[mt][3] = *(uint32_t*)&Ahi[o1 + 8];
                al[mt][0] = *(uint32_t*)&Alo[o0];
                al[mt][1] = *(uint32_t*)&Alo[o1];
                al[mt][2] = *(uint32_t*)&Alo[o0 + 8];
                al[mt][3] = *(uint32_t*)&Alo[o1 + 8];
            }
            #pragma unroll
            for (int nt = 0; nt < 4; nt++) {
                int n = wcol * 32 + nt * 8 + r;
                int ob = n * BW + (kk >> 1) + q;
                uint32_t bh[2], bl[2];
                bh[0] = Bhi32[ob];
                bh[1] = Bhi32[ob + 4];
                bl[0] = Blo32[ob];
                bl[1] = Blo32[ob + 4];
                #pragma unroll
                for (int mt = 0; mt < 2; mt++) {
                    mma16816(acc[mt][nt], ah[mt], bh);
                    mma16816(acc[mt][nt], al[mt], bh);
                    mma16816(acc[mt][nt], ah[mt], bl);
                }
            }
        }
        __syncthreads();
    }

    // ---- epilogue: bias + relu, direct gmem stores ----
    #pragma unroll
    for (int nt = 0; nt < 4; nt++) {
        int gc = nBase + wcol * 32 + nt * 8 + c2;
        float bx = __ldg(&bias[gc]), by = __ldg(&bias[gc + 1]);
        #pragma unroll
        for (int mt = 0; mt < 2; mt++) {
            int gr = mBase + wrow * 32 + mt * 16 + r;
            float2 o0, o1;
            o0.x = acc[mt][nt][0] + bx; o0.y = acc[mt][nt][1] + by;
            o1.x = acc[mt][nt][2] + bx; o1.y = acc[mt][nt][3] + by;
            if (RELU) {
                o0.x = fmaxf(o0.x, 0.f); o0.y = fmaxf(o0.y, 0.f);
                o1.x = fmaxf(o1.x, 0.f); o1.y = fmaxf(o1.y, 0.f);
            }
            if (gr < NN)     *(float2*)(C + (size_t)gr * NCT + gc) = o0;
            if (gr + 8 < NN) *(float2*)(C + (size_t)(gr + 8) * NCT + gc) = o1;
        }
    }
}

// ---------------- propagation hop: gather over dest-CSR ----------------------
__global__ void __launch_bounds__(256) k_hop(int hop) {
    int gw = (blockIdx.x * blockDim.x + threadIdx.x) >> 5;
    if (gw >= NN) return;
    int lane = threadIdx.x & 31;
    int hf = lane >> 4, sub = lane & 15;
    const float4* __restrict__ hprev = (const float4*)(g_h + (size_t)hop * NN * DO);
    float4* __restrict__ hnew = (float4*)(g_h + (size_t)(hop + 1) * NN * DO);
    int start = g_off[gw], end = g_off[gw + 1];

    float ax = 0.f, ay = 0.f, az = 0.f, aw = 0.f;
    for (int base = start; base < end; base += 32) {
        int i = base + lane;
        int2 meta = make_int2(0, 0);
        if (i < end) meta = g_csr[i];
        int lim = end - base; if (lim > 32) lim = 32;
        for (int j2 = 0; j2 < lim; j2 += 2) {
            int j = (j2 + hf) & 31;
            int s = __shfl_sync(0xffffffffu, meta.x, j);
            float w = __int_as_float(__shfl_sync(0xffffffffu, meta.y, j));
            float4 v = __ldg(&hprev[s * 16 + sub]);
            ax = fmaf(w, v.x, ax); ay = fmaf(w, v.y, ay);
            az = fmaf(w, v.z, az); aw = fmaf(w, v.w, aw);
        }
    }
    ax += __shfl_xor_sync(0xffffffffu, ax, 16);
    ay += __shfl_xor_sync(0xffffffffu, ay, 16);
    az += __shfl_xor_sync(0xffffffffu, az, 16);
    aw += __shfl_xor_sync(0xffffffffu, aw, 16);
    if (hf == 0) {
        float d = g_dinv[gw];
        float w = d * d;
        float4 v = __ldg(&hprev[gw * 16 + sub]);
        hnew[gw * 16 + sub] = make_float4(fmaf(w, v.x, ax), fmaf(w, v.y, ay),
                                          fmaf(w, v.z, az), fmaf(w, v.w, aw));
    }
}

// ---------------- adaptive hop pooling epilogue ------------------------------
__global__ void __launch_bounds__(256) k_pool(const float* __restrict__ pw,
                                              const float* __restrict__ pb,
                                              float* __restrict__ out) {
    int gw = (blockIdx.x * blockDim.x + threadIdx.x) >> 5;
    if (gw >= NN) return;
    int lane = threadIdx.x & 31;
    float2 w2 = ((const float2*)pw)[lane];
    float bias = pb[0];
    float ox = 0.f, oy = 0.f;
    #pragma unroll
    for (int k = 0; k <= KHOPS; k++) {
        const float2* hp = (const float2*)(g_h + (size_t)k * NN * DO + (size_t)gw * DO);
        float2 v = __ldg(&hp[lane]);
        float p = v.x * w2.x + v.y * w2.y;
        #pragma unroll
        for (int o = 16; o; o >>= 1) p += __shfl_xor_sync(0xffffffffu, p, o);
        float sc = 1.f / (1.f + expf(-(p + bias)));
        ox = fmaf(sc, v.x, ox);
        oy = fmaf(sc, v.y, oy);
    }
    ((float2*)(out + (size_t)gw * DO))[lane] = make_float2(ox, oy);
}

// ---------------- launch -----------------------------------------------------
extern "C" void kernel_launch(void* const* d_in, const int* in_sizes, int n_in,
                              void* d_out, int out_size) {
    const float* x  = (const float*)d_in[0];
    const void*  ei = d_in[1];
    const float* W1 = (const float*)d_in[2];
    const float* b1 = (const float*)d_in[3];
    const float* W2 = (const float*)d_in[4];
    const float* b2 = (const float*)d_in[5];
    const float* pw = (const float*)d_in[6];
    const float* pb = (const float*)d_in[7];
    float* out = (float*)d_out;

    k_initdet<<<392, 256>>>((const int*)ei);                             // #0
    k_count  <<<(EE + 255) / 256, 256>>>(ei);                            // #1
    k_scanA  <<<NB_SCAN, 1024>>>();                                      // #2 (+dinv)
    k_gemm_mma<128, 256, true,  true ><<<dim3(1563, 2), 256>>>(x, W1, b1);        // #3 (profiled)
    k_scanC  <<<NB_SCAN, 1024>>>();                                      // #4
    k_fill   <<<(EE + 255) / 256, 256>>>(ei);                            // #5
    k_gemm_mma<64,  128, false, false><<<dim3(1563, 1), 128>>>(nullptr, W2, b2);  // #6

    for (int k = 0; k < KHOPS; k++)                                      // #7..16
        k_hop<<<NN / 8, 256>>>(k);

    k_pool<<<NN / 8, 256>>>(pw, pb, out);                                // #17
}

// round 9
// speedup vs baseline: 1.4772x; 1.1619x over previous
#include <cuda_runtime.h>
#include <cuda_bf16.h>
#include <cuda_fp16.h>
#include <cstdint>

#define NN 100000
#define EE 3200000
#define DINF 256
#define DHID 256
#define DO 64
#define KHOPS 10
#define NB_SCAN 98   // ceil(100000/1024)

// ---------------- scratch (device globals; no allocation allowed) -------------
__device__ __align__(16) float  g_hidden[(size_t)NN * DHID];             // 102.4 MB
__device__ __align__(16) __half g_hh[(size_t)(KHOPS + 1) * NN * DO];     // 140.8 MB
__device__ float g_dinv[NN];
__device__ int   g_deg[NN];
__device__ int   g_cursor[NN];
__device__ int   g_off[NN + 1];
__device__ int2  g_csr[EE];                                              // {src, norm}
__device__ int   g_bsum[NB_SCAN];
__device__ int   g_is64;
// pre-split weights, packed k-pair layout [tile][k0][n][k2] (uint32 = 2 bf16)
__device__ __align__(16) uint32_t g_w1hi[2 * 8 * 128 * 16];
__device__ __align__(16) uint32_t g_w1lo[2 * 8 * 128 * 16];
__device__ __align__(16) uint32_t g_w2hi[8 * 64 * 16];
__device__ __align__(16) uint32_t g_w2lo[8 * 64 * 16];

// ---------------- edge dtype helpers ------------------------------------------
__device__ __forceinline__ int edge_at(const void* eiv, long long idx) {
    int v;
    if (g_is64) v = (int)((const long long*)eiv)[idx];
    else        v = ((const int*)eiv)[idx];
    return min(max(v, 0), NN - 1);
}

// ---------------- weight split precompute --------------------------------------
__device__ __forceinline__ void split1(float x, __nv_bfloat16& h, __nv_bfloat16& l) {
    h = __float2bfloat16_rn(x);
    l = __float2bfloat16_rn(x - __bfloat162float(h));
}
__global__ void k_prepW(const float* __restrict__ W1, const float* __restrict__ W2) {
    int t = blockIdx.x * blockDim.x + threadIdx.x;
    if (t < 4096) {                      // W1: 256 n x 16 k2
        int nG = t >> 4, k2 = t & 15;
        int ty = nG >> 7, n = nG & 127;
        #pragma unroll
        for (int k0c = 0; k0c < 8; k0c++) {
            int k = k0c * 32 + k2 * 2;
            float w0 = W1[(size_t)k * DHID + nG];
            float w1 = W1[(size_t)(k + 1) * DHID + nG];
            __nv_bfloat16 h0, l0, h1, l1;
            split1(w0, h0, l0); split1(w1, h1, l1);
            __nv_bfloat162 hp; hp.x = h0; hp.y = h1;
            __nv_bfloat162 lp; lp.x = l0; lp.y = l1;
            int idx = ((ty * 8 + k0c) * 128 + n) * 16 + k2;
            g_w1hi[idx] = *(uint32_t*)&hp;
            g_w1lo[idx] = *(uint32_t*)&lp;
        }
    } else if (t < 4096 + 1024) {        // W2: 64 n x 16 k2
        int u = t - 4096;
        int nG = u >> 4, k2 = u & 15;
        #pragma unroll
        for (int k0c = 0; k0c < 8; k0c++) {
            int k = k0c * 32 + k2 * 2;
            float w0 = W2[(size_t)k * DO + nG];
            float w1 = W2[(size_t)(k + 1) * DO + nG];
            __nv_bfloat16 h0, l0, h1, l1;
            split1(w0, h0, l0); split1(w1, h1, l1);
            __nv_bfloat162 hp; hp.x = h0; hp.y = h1;
            __nv_bfloat162 lp; lp.x = l0; lp.y = l1;
            int idx = (k0c * 64 + nG) * 16 + k2;
            g_w2hi[idx] = *(uint32_t*)&hp;
            g_w2lo[idx] = *(uint32_t*)&lp;
        }
    }
}

// ---------------- init + dtype detect (fused) ----------------------------------
__global__ void k_initdet(const int* __restrict__ w) {
    int i = blockIdx.x * blockDim.x + threadIdx.x;
    if (i < NN) { g_deg[i] = 1; g_cursor[i] = 0; }
    if (blockIdx.x == 391) {
        __shared__ int nz;
        if (threadIdx.x == 0) nz = 0;
        __syncthreads();
        int local = 0;
        for (int j = threadIdx.x; j < 2048; j += 256)
            if (w[2 * j + 1] != 0) local = 1;
        if (local) atomicAdd(&nz, 1);
        __syncthreads();
        if (threadIdx.x == 0) g_is64 = (nz == 0) ? 1 : 0;
    }
}

__global__ void k_count(const void* __restrict__ eiv) {
    int e = blockIdx.x * blockDim.x + threadIdx.x;
    if (e < EE) atomicAdd(&g_deg[edge_at(eiv, (long long)EE + e)], 1);
}

// ---------------- scanA (+dinv) -------------------------------------------------
__global__ void k_scanA() {
    int tid = threadIdx.x;
    int i = blockIdx.x * 1024 + tid;
    int v = 0;
    if (i < NN) {
        int d = g_deg[i];
        v = d - 1;
        g_dinv[i] = rsqrtf((float)d);
    }
    int lane = tid & 31, wid = tid >> 5;
    int x = v;
    #pragma unroll
    for (int o = 1; o < 32; o <<= 1) {
        int t = __shfl_up_sync(0xffffffffu, x, o);
        if (lane >= o) x += t;
    }
    __shared__ int wsum[32];
    if (lane == 31) wsum[wid] = x;
    __syncthreads();
    if (wid == 0) {
        int y = wsum[lane];
        #pragma unroll
        for (int o = 1; o < 32; o <<= 1) {
            int t = __shfl_up_sync(0xffffffffu, y, o);
            if (lane >= o) y += t;
        }
        wsum[lane] = y;
    }
    __syncthreads();
    int incl = x + (wid > 0 ? wsum[wid - 1] : 0);
    if (i < NN) g_off[i] = incl - v;
    if (tid == 1023) g_bsum[blockIdx.x] = incl;
}

// ---------------- scanC ---------------------------------------------------------
__global__ void k_scanC() {
    __shared__ int pre;
    if (threadIdx.x == 0) {
        int s = 0;
        for (int b = 0; b < blockIdx.x; b++) s += g_bsum[b];
        pre = s;
    }
    __syncthreads();
    int i = blockIdx.x * 1024 + threadIdx.x;
    if (i < NN) g_off[i] += pre;
    if (i == 0) g_off[NN] = EE;
}

// ---------------- CSR fill ------------------------------------------------------
__global__ void k_fill(const void* __restrict__ eiv) {
    int e = blockIdx.x * blockDim.x + threadIdx.x;
    if (e < EE) {
        int r = edge_at(eiv, e);
        int c = edge_at(eiv, (long long)EE + e);
        float w = g_dinv[r] * g_dinv[c];
        int p = g_off[c] + atomicAdd(&g_cursor[c], 1);
        if (p < EE) g_csr[p] = make_int2(r, __float_as_int(w));
    }
}

// ================= split-bf16 mma.sync GEMM ====================================
__device__ __forceinline__ void split_pack(float a, float b, uint32_t& hi, uint32_t& lo) {
    __nv_bfloat16 ah, al, bh, bl;
    split1(a, ah, al); split1(b, bh, bl);
    __nv_bfloat162 h2; h2.x = ah; h2.y = bh;
    __nv_bfloat162 l2; l2.x = al; l2.y = bl;
    hi = *(uint32_t*)&h2;
    lo = *(uint32_t*)&l2;
}
__device__ __forceinline__ void mma16816(float* d, const uint32_t* a, const uint32_t* b) {
    asm volatile(
        "mma.sync.aligned.m16n8k16.row.col.f32.bf16.bf16.f32 "
        "{%0,%1,%2,%3}, {%4,%5,%6,%7}, {%8,%9}, {%0,%1,%2,%3};"
        : "+f"(d[0]), "+f"(d[1]), "+f"(d[2]), "+f"(d[3])
        : "r"(a[0]), "r"(a[1]), "r"(a[2]), "r"(a[3]), "r"(b[0]), "r"(b[1]));
}

#define KPAD 40    // A smem k-stride in bf16 elems
#define BW 20      // B smem n-stride in uint32 (16 k-pairs + 4 pad)
// FIRST: A=x (fp32 split on the fly), C=g_hidden fp32, relu.
// !FIRST: A=g_hidden, C=g_hh hop-0 slice (fp16).
template<int BN, int T, bool RELU, bool FIRST>
__global__ void __launch_bounds__(T) k_gemm_mma(
    const float* __restrict__ Ain, const float* __restrict__ bias) {
    const int NCT = FIRST ? DHID : DO;
    const float* __restrict__ A = FIRST ? Ain : g_hidden;
    const int WCOLS = BN / 32;

    __shared__ __align__(16) __nv_bfloat16 Ahi[64 * KPAD], Alo[64 * KPAD];
    __shared__ __align__(16) uint32_t Bhi32[BN * BW], Blo32[BN * BW];

    int tid = threadIdx.x;
    int wid = tid >> 5, lane = tid & 31;
    int wrow = wid / WCOLS, wcol = wid % WCOLS;
    int mBase = blockIdx.x * 64;
    int nBase = blockIdx.y * BN;
    int r = lane >> 2, q = lane & 3, c2 = q * 2;

    float acc[2][4][4];
    #pragma unroll
    for (int i = 0; i < 2; i++)
        #pragma unroll
        for (int j = 0; j < 4; j++)
            #pragma unroll
            for (int p = 0; p < 4; p++) acc[i][j][p] = 0.f;

    for (int k0 = 0; k0 < 256; k0 += 32) {
        // ---- A tile 64x32 fp32 -> split bf16 smem ----
        #pragma unroll
        for (int it = 0; it < 512 / T; it++) {
            int L = tid + it * T;
            int row = L >> 3, f4 = L & 7;
            int rowG = min(mBase + row, NN - 1);
            float4 v = __ldg((const float4*)(A + (size_t)rowG * 256 + k0 + f4 * 4));
            int idx = row * KPAD + f4 * 4;
            uint32_t h01, l01, h23, l23;
            split_pack(v.x, v.y, h01, l01);
            split_pack(v.z, v.w, h23, l23);
            uint2 hh; hh.x = h01; hh.y = h23;
            uint2 ll; ll.x = l01; ll.y = l23;
            *(uint2*)&Ahi[idx] = hh;
            *(uint2*)&Alo[idx] = ll;
        }
        // ---- B tile: straight uint4 copy from pre-split gmem ----
        {
            size_t base4 = (size_t)((FIRST ? blockIdx.y * 8 : 0) + (k0 >> 5)) * BN * 4;
            const uint4* shi = (const uint4*)(FIRST ? g_w1hi : g_w2hi) + base4;
            const uint4* slo = (const uint4*)(FIRST ? g_w1lo : g_w2lo) + base4;
            #pragma unroll
            for (int i = 0; i < (BN * 4) / T; i++) {
                int idx4 = tid + i * T;
                int n = idx4 >> 2, k2 = (idx4 & 3) * 4;
                uint4 vh = __ldg(&shi[idx4]);
                uint4 vl = __ldg(&slo[idx4]);
                *(uint4*)&Bhi32[n * BW + k2] = vh;
                *(uint4*)&Blo32[n * BW + k2] = vl;
            }
        }
        __syncthreads();

        #pragma unroll
        for (int kk = 0; kk < 32; kk += 16) {
            uint32_t ah[2][4], al[2][4];
            #pragma unroll
            for (int mt = 0; mt < 2; mt++) {
                int m = wrow * 32 + mt * 16 + r;
                int o0 = m * KPAD + kk + c2;
                int o1 = (m + 8) * KPAD + kk + c2;
                ah[mt][0] = *(uint32_t*)&Ahi[o0];
                ah[mt][1] = *(uint32_t*)&Ahi[o1];
                ah[mt][2] = *(uint32_t*)&Ahi[o0 + 8];
                ah[mt][3] = *(uint32_t*)&Ahi[o1 + 8];
                al[mt][0] = *(uint32_t*)&Alo[o0];
                al[mt][1] = *(uint32_t*)&Alo[o1];
                al[mt][2] = *(uint32_t*)&Alo[o0 + 8];
                al[mt][3] = *(uint32_t*)&Alo[o1 + 8];
            }
            #pragma unroll
            for (int nt = 0; nt < 4; nt++) {
                int n = wcol * 32 + nt * 8 + r;
                int ob = n * BW + (kk >> 1) + q;
                uint32_t bh[2], bl[2];
                bh[0] = Bhi32[ob];
                bh[1] = Bhi32[ob + 4];
                bl[0] = Blo32[ob];
                bl[1] = Blo32[ob + 4];
                #pragma unroll
                for (int mt = 0; mt < 2; mt++) {
                    mma16816(acc[mt][nt], ah[mt], bh);
                    mma16816(acc[mt][nt], al[mt], bh);
                    mma16816(acc[mt][nt], ah[mt], bl);
                }
            }
        }
        __syncthreads();
    }

    // ---- epilogue ----
    #pragma unroll
    for (int nt = 0; nt < 4; nt++) {
        int gc = nBase + wcol * 32 + nt * 8 + c2;
        float bx = __ldg(&bias[gc]), by = __ldg(&bias[gc + 1]);
        #pragma unroll
        for (int mt = 0; mt < 2; mt++) {
            int gr = mBase + wrow * 32 + mt * 16 + r;
            float2 o0, o1;
            o0.x = acc[mt][nt][0] + bx; o0.y = acc[mt][nt][1] + by;
            o1.x = acc[mt][nt][2] + bx; o1.y = acc[mt][nt][3] + by;
            if (RELU) {
                o0.x = fmaxf(o0.x, 0.f); o0.y = fmaxf(o0.y, 0.f);
                o1.x = fmaxf(o1.x, 0.f); o1.y = fmaxf(o1.y, 0.f);
            }
            if (FIRST) {
                if (gr < NN)     *(float2*)(g_hidden + (size_t)gr * NCT + gc) = o0;
                if (gr + 8 < NN) *(float2*)(g_hidden + (size_t)(gr + 8) * NCT + gc) = o1;
            } else {
                if (gr < NN)     *(__half2*)(g_hh + (size_t)gr * DO + gc) = __floats2half2_rn(o0.x, o0.y);
                if (gr + 8 < NN) *(__half2*)(g_hh + (size_t)(gr + 8) * DO + gc) = __floats2half2_rn(o1.x, o1.y);
            }
        }
    }
}

// ---------------- propagation hop: fp16 gather over dest-CSR -------------------
// warp per node; 16 lanes x uint2 (4 halves) cover 64 features; two edge streams
__global__ void __launch_bounds__(256) k_hop(int hop) {
    int gw = (blockIdx.x * blockDim.x + threadIdx.x) >> 5;
    if (gw >= NN) return;
    int lane = threadIdx.x & 31;
    int hf = lane >> 4, sub = lane & 15;
    const uint2* __restrict__ hprev = (const uint2*)(g_hh + (size_t)hop * NN * DO);
    uint2* __restrict__ hnew = (uint2*)(g_hh + (size_t)(hop + 1) * NN * DO);
    int start = g_off[gw], end = g_off[gw + 1];

    float ax = 0.f, ay = 0.f, az = 0.f, aw = 0.f;
    for (int base = start; base < end; base += 32) {
        int i = base + lane;
        int2 meta = make_int2(0, 0);
        if (i < end) meta = g_csr[i];
        int lim = end - base; if (lim > 32) lim = 32;
        for (int j2 = 0; j2 < lim; j2 += 2) {
            int j = (j2 + hf) & 31;
            int s = __shfl_sync(0xffffffffu, meta.x, j);
            float w = __int_as_float(__shfl_sync(0xffffffffu, meta.y, j));
            uint2 u = __ldg(&hprev[s * 16 + sub]);
            float2 f0 = __half22float2(*(__half2*)&u.x);
            float2 f1 = __half22float2(*(__half2*)&u.y);
            ax = fmaf(w, f0.x, ax); ay = fmaf(w, f0.y, ay);
            az = fmaf(w, f1.x, az); aw = fmaf(w, f1.y, aw);
        }
    }
    ax += __shfl_xor_sync(0xffffffffu, ax, 16);
    ay += __shfl_xor_sync(0xffffffffu, ay, 16);
    az += __shfl_xor_sync(0xffffffffu, az, 16);
    aw += __shfl_xor_sync(0xffffffffu, aw, 16);
    if (hf == 0) {
        float d = g_dinv[gw];
        float w = d * d;                    // self-loop
        uint2 u = __ldg(&hprev[gw * 16 + sub]);
        float2 f0 = __half22float2(*(__half2*)&u.x);
        float2 f1 = __half22float2(*(__half2*)&u.y);
        uint2 o;
        *(__half2*)&o.x = __floats2half2_rn(fmaf(w, f0.x, ax), fmaf(w, f0.y, ay));
        *(__half2*)&o.y = __floats2half2_rn(fmaf(w, f1.x, az), fmaf(w, f1.y, aw));
        hnew[gw * 16 + sub] = o;
    }
}

// ---------------- adaptive hop pooling epilogue --------------------------------
__global__ void __launch_bounds__(256) k_pool(const float* __restrict__ pw,
                                              const float* __restrict__ pb,
                                              float* __restrict__ out) {
    int gw = (blockIdx.x * blockDim.x + threadIdx.x) >> 5;
    if (gw >= NN) return;
    int lane = threadIdx.x & 31;
    float2 w2 = ((const float2*)pw)[lane];
    float bias = pb[0];
    float ox = 0.f, oy = 0.f;
    #pragma unroll
    for (int k = 0; k <= KHOPS; k++) {
        const __half2* hp = (const __half2*)(g_hh + (size_t)k * NN * DO + (size_t)gw * DO);
        float2 v = __half22float2(__ldg(&hp[lane]));
        float p = v.x * w2.x + v.y * w2.y;
        #pragma unroll
        for (int o = 16; o; o >>= 1) p += __shfl_xor_sync(0xffffffffu, p, o);
        float sc = 1.f / (1.f + expf(-(p + bias)));
        ox = fmaf(sc, v.x, ox);
        oy = fmaf(sc, v.y, oy);
    }
    ((float2*)(out + (size_t)gw * DO))[lane] = make_float2(ox, oy);
}

// ---------------- launch -------------------------------------------------------
extern "C" void kernel_launch(void* const* d_in, const int* in_sizes, int n_in,
                              void* d_out, int out_size) {
    const float* x  = (const float*)d_in[0];
    const void*  ei = d_in[1];
    const float* W1 = (const float*)d_in[2];
    const float* b1 = (const float*)d_in[3];
    const float* W2 = (const float*)d_in[4];
    const float* b2 = (const float*)d_in[5];
    const float* pw = (const float*)d_in[6];
    const float* pb = (const float*)d_in[7];
    float* out = (float*)d_out;

    k_prepW  <<<20, 256>>>(W1, W2);                                          // #0
    k_initdet<<<392, 256>>>((const int*)ei);                                 // #1
    k_gemm_mma<128, 256, true,  true ><<<dim3(1563, 2), 256>>>(x, b1);       // #2
    k_gemm_mma<64,  128, false, false><<<dim3(1563, 1), 128>>>(nullptr, b2); // #3 (profiled)
    k_count  <<<(EE + 255) / 256, 256>>>(ei);                                // #4
    k_scanA  <<<NB_SCAN, 1024>>>();                                          // #5
    k_scanC  <<<NB_SCAN, 1024>>>();                                          // #6
    k_fill   <<<(EE + 255) / 256, 256>>>(ei);                                // #7

    for (int k = 0; k < KHOPS; k++)                                          // #8..17
        k_hop<<<NN / 8, 256>>>(k);

    k_pool<<<NN / 8, 256>>>(pw, pb, out);                                    // #18
}

// round 15
// speedup vs baseline: 1.5055x; 1.0191x over previous
#include <cuda_runtime.h>
#include <cuda_bf16.h>
#include <cuda_fp16.h>
#include <cstdint>

#define NN 100000
#define EE 3200000
#define DINF 256
#define DHID 256
#define DO 64
#define KHOPS 10
#define NB_SCAN 98   // ceil(100000/1024)

// ---------------- scratch (device globals; no allocation allowed) -------------
__device__ __align__(16) __nv_bfloat16 g_hidden[(size_t)NN * DHID];      // 51.2 MB (bf16 hi)
__device__ __align__(16) __half g_hh[(size_t)(KHOPS + 1) * NN * DO];     // 140.8 MB
__device__ float g_dinv[NN];
__device__ int   g_deg[NN];
__device__ int   g_cursor[NN];
__device__ int   g_off[NN + 1];
__device__ int2  g_csr[EE];                                              // {src, norm}
__device__ int   g_bsum[NB_SCAN];
__device__ int   g_is64;
// pre-split bf16 weights, packed k-pair layout [tile][k0][n][k2] (uint32 = 2 bf16)
__device__ __align__(16) uint32_t g_w1hi[2 * 8 * 128 * 16];
__device__ __align__(16) uint32_t g_w1lo[2 * 8 * 128 * 16];
__device__ __align__(16) uint32_t g_w2hi[8 * 64 * 16];
__device__ __align__(16) uint32_t g_w2lo[8 * 64 * 16];

// ---------------- edge dtype helpers ------------------------------------------
__device__ __forceinline__ int edge_at(const void* eiv, long long idx) {
    int v;
    if (g_is64) v = (int)((const long long*)eiv)[idx];
    else        v = ((const int*)eiv)[idx];
    return min(max(v, 0), NN - 1);
}

// ---------------- weight split precompute --------------------------------------
__device__ __forceinline__ void split1(float x, __nv_bfloat16& h, __nv_bfloat16& l) {
    h = __float2bfloat16_rn(x);
    l = __float2bfloat16_rn(x - __bfloat162float(h));
}
__global__ void k_prepW(const float* __restrict__ W1, const float* __restrict__ W2) {
    int t = blockIdx.x * blockDim.x + threadIdx.x;
    if (t < 4096) {                      // W1: 256 n x 16 k2
        int nG = t >> 4, k2 = t & 15;
        int ty = nG >> 7, n = nG & 127;
        #pragma unroll
        for (int k0c = 0; k0c < 8; k0c++) {
            int k = k0c * 32 + k2 * 2;
            float w0 = W1[(size_t)k * DHID + nG];
            float w1 = W1[(size_t)(k + 1) * DHID + nG];
            __nv_bfloat16 h0, l0, h1, l1;
            split1(w0, h0, l0); split1(w1, h1, l1);
            __nv_bfloat162 hp; hp.x = h0; hp.y = h1;
            __nv_bfloat162 lp; lp.x = l0; lp.y = l1;
            int idx = ((ty * 8 + k0c) * 128 + n) * 16 + k2;
            g_w1hi[idx] = *(uint32_t*)&hp;
            g_w1lo[idx] = *(uint32_t*)&lp;
        }
    } else if (t < 4096 + 1024) {        // W2: 64 n x 16 k2
        int u = t - 4096;
        int nG = u >> 4, k2 = u & 15;
        #pragma unroll
        for (int k0c = 0; k0c < 8; k0c++) {
            int k = k0c * 32 + k2 * 2;
            float w0 = W2[(size_t)k * DO + nG];
            float w1 = W2[(size_t)(k + 1) * DO + nG];
            __nv_bfloat16 h0, l0, h1, l1;
            split1(w0, h0, l0); split1(w1, h1, l1);
            __nv_bfloat162 hp; hp.x = h0; hp.y = h1;
            __nv_bfloat162 lp; lp.x = l0; lp.y = l1;
            int idx = (k0c * 64 + nG) * 16 + k2;
            g_w2hi[idx] = *(uint32_t*)&hp;
            g_w2lo[idx] = *(uint32_t*)&lp;
        }
    }
}

// ---------------- init + dtype detect (fused) ----------------------------------
__global__ void k_initdet(const int* __restrict__ w) {
    int i = blockIdx.x * blockDim.x + threadIdx.x;
    if (i < NN) { g_deg[i] = 1; g_cursor[i] = 0; }
    if (blockIdx.x == 391) {
        __shared__ int nz;
        if (threadIdx.x == 0) nz = 0;
        __syncthreads();
        int local = 0;
        for (int j = threadIdx.x; j < 2048; j += 256)
            if (w[2 * j + 1] != 0) local = 1;
        if (local) atomicAdd(&nz, 1);
        __syncthreads();
        if (threadIdx.x == 0) g_is64 = (nz == 0) ? 1 : 0;
    }
}

__global__ void k_count(const void* __restrict__ eiv) {
    int e = blockIdx.x * blockDim.x + threadIdx.x;
    if (e < EE) atomicAdd(&g_deg[edge_at(eiv, (long long)EE + e)], 1);
}

// ---------------- scanA (+dinv) -------------------------------------------------
__global__ void k_scanA() {
    int tid = threadIdx.x;
    int i = blockIdx.x * 1024 + tid;
    int v = 0;
    if (i < NN) {
        int d = g_deg[i];
        v = d - 1;
        g_dinv[i] = rsqrtf((float)d);
    }
    int lane = tid & 31, wid = tid >> 5;
    int x = v;
    #pragma unroll
    for (int o = 1; o < 32; o <<= 1) {
        int t = __shfl_up_sync(0xffffffffu, x, o);
        if (lane >= o) x += t;
    }
    __shared__ int wsum[32];
    if (lane == 31) wsum[wid] = x;
    __syncthreads();
    if (wid == 0) {
        int y = wsum[lane];
        #pragma unroll
        for (int o = 1; o < 32; o <<= 1) {
            int t = __shfl_up_sync(0xffffffffu, y, o);
            if (lane >= o) y += t;
        }
        wsum[lane] = y;
    }
    __syncthreads();
    int incl = x + (wid > 0 ? wsum[wid - 1] : 0);
    if (i < NN) g_off[i] = incl - v;
    if (tid == 1023) g_bsum[blockIdx.x] = incl;
}

// ---------------- scanC ---------------------------------------------------------
__global__ void k_scanC() {
    __shared__ int pre;
    if (threadIdx.x == 0) {
        int s = 0;
        for (int b = 0; b < blockIdx.x; b++) s += g_bsum[b];
        pre = s;
    }
    __syncthreads();
    int i = blockIdx.x * 1024 + threadIdx.x;
    if (i < NN) g_off[i] += pre;
    if (i == 0) g_off[NN] = EE;
}

// ---------------- CSR fill ------------------------------------------------------
__global__ void k_fill(const void* __restrict__ eiv) {
    int e = blockIdx.x * blockDim.x + threadIdx.x;
    if (e < EE) {
        int r = edge_at(eiv, e);
        int c = edge_at(eiv, (long long)EE + e);
        float w = g_dinv[r] * g_dinv[c];
        int p = g_off[c] + atomicAdd(&g_cursor[c], 1);
        if (p < EE) g_csr[p] = make_int2(r, __float_as_int(w));
    }
}

// ================= bf16 mma.sync GEMMs =========================================
__device__ __forceinline__ void split_pack(float a, float b, uint32_t& hi, uint32_t& lo) {
    __nv_bfloat16 ah, al, bh, bl;
    split1(a, ah, al); split1(b, bh, bl);
    __nv_bfloat162 h2; h2.x = ah; h2.y = bh;
    __nv_bfloat162 l2; l2.x = al; l2.y = bl;
    hi = *(uint32_t*)&h2;
    lo = *(uint32_t*)&l2;
}
__device__ __forceinline__ void mma16816(float* d, const uint32_t* a, const uint32_t* b) {
    asm volatile(
        "mma.sync.aligned.m16n8k16.row.col.f32.bf16.bf16.f32 "
        "{%0,%1,%2,%3}, {%4,%5,%6,%7}, {%8,%9}, {%0,%1,%2,%3};"
        : "+f"(d[0]), "+f"(d[1]), "+f"(d[2]), "+f"(d[3])
        : "r"(a[0]), "r"(a[1]), "r"(a[2]), "r"(a[3]), "r"(b[0]), "r"(b[1]));
}

#define KPAD 40    // A smem k-stride in bf16 elems
#define BW 20      // B smem n-stride in uint32 (16 k-pairs + 4 pad)

// ---- GEMM1: hidden = relu(x @ W1 + b1), 3-pass split-bf16, bf16-hi output ----
// BM=64, BN=128, T=256. Grid (1563, 2).
__global__ void __launch_bounds__(256) k_gemm1(
    const float* __restrict__ A, const float* __restrict__ bias) {
    __shared__ __align__(16) __nv_bfloat16 Ahi[64 * KPAD], Alo[64 * KPAD];
    __shared__ __align__(16) uint32_t Bhi32[128 * BW], Blo32[128 * BW];

    int tid = threadIdx.x;
    int wid = tid >> 5, lane = tid & 31;
    int wrow = wid >> 2, wcol = wid & 3;
    int mBase = blockIdx.x * 64;
    int nBase = blockIdx.y * 128;
    int r = lane >> 2, q = lane & 3, c2 = q * 2;

    float acc[2][4][4];
    #pragma unroll
    for (int i = 0; i < 2; i++)
        #pragma unroll
        for (int j = 0; j < 4; j++)
            #pragma unroll
            for (int p = 0; p < 4; p++) acc[i][j][p] = 0.f;

    for (int k0 = 0; k0 < 256; k0 += 32) {
        // A tile 64x32 fp32 -> split bf16 smem
        #pragma unroll
        for (int it = 0; it < 2; it++) {
            int L = tid + it * 256;
            int row = L >> 3, f4 = L & 7;
            int rowG = min(mBase + row, NN - 1);
            float4 v = __ldg((const float4*)(A + (size_t)rowG * 256 + k0 + f4 * 4));
            int idx = row * KPAD + f4 * 4;
            uint32_t h01, l01, h23, l23;
            split_pack(v.x, v.y, h01, l01);
            split_pack(v.z, v.w, h23, l23);
            uint2 hh; hh.x = h01; hh.y = h23;
            uint2 ll; ll.x = l01; ll.y = l23;
            *(uint2*)&Ahi[idx] = hh;
            *(uint2*)&Alo[idx] = ll;
        }
        // B tile: straight uint4 copy from pre-split gmem
        {
            size_t base4 = (size_t)(blockIdx.y * 8 + (k0 >> 5)) * 128 * 4;
            const uint4* shi = (const uint4*)g_w1hi + base4;
            const uint4* slo = (const uint4*)g_w1lo + base4;
            #pragma unroll
            for (int i = 0; i < 2; i++) {
                int idx4 = tid + i * 256;
                int n = idx4 >> 2, k2 = (idx4 & 3) * 4;
                uint4 vh = __ldg(&shi[idx4]);
                uint4 vl = __ldg(&slo[idx4]);
                *(uint4*)&Bhi32[n * BW + k2] = vh;
                *(uint4*)&Blo32[n * BW + k2] = vl;
            }
        }
        __syncthreads();

        #pragma unroll
        for (int kk = 0; kk < 32; kk += 16) {
            uint32_t ah[2][4], al[2][4];
            #pragma unroll
            for (int mt = 0; mt < 2; mt++) {
                int m = wrow * 32 + mt * 16 + r;
                int o0 = m * KPAD + kk + c2;
                int o1 = (m + 8) * KPAD + kk + c2;
                ah[mt][0] = *(uint32_t*)&Ahi[o0];
                ah[mt][1] = *(uint32_t*)&Ahi[o1];
                ah[mt][2] = *(uint32_t*)&Ahi[o0 + 8];
                ah[mt][3] = *(uint32_t*)&Ahi[o1 + 8];
                al[mt][0] = *(uint32_t*)&Alo[o0];
                al[mt][1] = *(uint32_t*)&Alo[o1];
                al[mt][2] = *(uint32_t*)&Alo[o0 + 8];
                al[mt][3] = *(uint32_t*)&Alo[o1 + 8];
            }
            #pragma unroll
            for (int nt = 0; nt < 4; nt++) {
                int n = wcol * 32 + nt * 8 + r;
                int ob = n * BW + (kk >> 1) + q;
                uint32_t bh[2], bl[2];
                bh[0] = Bhi32[ob];
                bh[1] = Bhi32[ob + 4];
                bl[0] = Blo32[ob];
                bl[1] = Blo32[ob + 4];
                #pragma unroll
                for (int mt = 0; mt < 2; mt++) {
                    mma16816(acc[mt][nt], ah[mt], bh);
                    mma16816(acc[mt][nt], al[mt], bh);
                    mma16816(acc[mt][nt], ah[mt], bl);
                }
            }
        }
        __syncthreads();
    }

    // epilogue: bias + relu -> bf16 hi
    #pragma unroll
    for (int nt = 0; nt < 4; nt++) {
        int gc = nBase + wcol * 32 + nt * 8 + c2;
        float bx = __ldg(&bias[gc]), by = __ldg(&bias[gc + 1]);
        #pragma unroll
        for (int mt = 0; mt < 2; mt++) {
            int gr = mBase + wrow * 32 + mt * 16 + r;
            float2 o0, o1;
            o0.x = fmaxf(acc[mt][nt][0] + bx, 0.f); o0.y = fmaxf(acc[mt][nt][1] + by, 0.f);
            o1.x = fmaxf(acc[mt][nt][2] + bx, 0.f); o1.y = fmaxf(acc[mt][nt][3] + by, 0.f);
            if (gr < NN)
                *(__nv_bfloat162*)(g_hidden + (size_t)gr * DHID + gc) = __floats2bfloat162_rn(o0.x, o0.y);
            if (gr + 8 < NN)
                *(__nv_bfloat162*)(g_hidden + (size_t)(gr + 8) * DHID + gc) = __floats2bfloat162_rn(o1.x, o1.y);
        }
    }
}

// ---- GEMM2: h0 = hidden_bf16 @ W2 + b2, 2-pass (A exact bf16, W split) --------
// BM=64, BN=64, T=128. Grid (1563, 1). Output fp16 into g_hh hop-0 slice.
__global__ void __launch_bounds__(128) k_gemm2(const float* __restrict__ bias) {
    __shared__ __align__(16) __nv_bfloat16 Ahi[64 * KPAD];
    __shared__ __align__(16) uint32_t Bhi32[64 * BW], Blo32[64 * BW];

    int tid = threadIdx.x;
    int wid = tid >> 5, lane = tid & 31;
    int wrow = wid >> 1, wcol = wid & 1;
    int mBase = blockIdx.x * 64;
    int r = lane >> 2, q = lane & 3, c2 = q * 2;

    float acc[2][4][4];
    #pragma unroll
    for (int i = 0; i < 2; i++)
        #pragma unroll
        for (int j = 0; j < 4; j++)
            #pragma unroll
            for (int p = 0; p < 4; p++) acc[i][j][p] = 0.f;

    for (int k0 = 0; k0 < 256; k0 += 32) {
        // A tile 64x32 bf16: straight uint4 copy (4 uint4 per row of 32 halfs)
        #pragma unroll
        for (int it = 0; it < 2; it++) {
            int L = tid + it * 128;
            int row = L >> 2, f8 = L & 3;
            int rowG = min(mBase + row, NN - 1);
            uint4 v = __ldg((const uint4*)(g_hidden + (size_t)rowG * DHID + k0) + f8);
            *(uint4*)&Ahi[row * KPAD + f8 * 8] = v;
        }
        // B tile: uint4 copy from pre-split gmem
        {
            size_t base4 = (size_t)(k0 >> 5) * 64 * 4;
            const uint4* shi = (const uint4*)g_w2hi + base4;
            const uint4* slo = (const uint4*)g_w2lo + base4;
            #pragma unroll
            for (int i = 0; i < 2; i++) {
                int idx4 = tid + i * 128;
                int n = idx4 >> 2, k2 = (idx4 & 3) * 4;
                uint4 vh = __ldg(&shi[idx4]);
                uint4 vl = __ldg(&slo[idx4]);
                *(uint4*)&Bhi32[n * BW + k2] = vh;
                *(uint4*)&Blo32[n * BW + k2] = vl;
            }
        }
        __syncthreads();

        #pragma unroll
        for (int kk = 0; kk < 32; kk += 16) {
            uint32_t ah[2][4];
            #pragma unroll
            for (int mt = 0; mt < 2; mt++) {
                int m = wrow * 32 + mt * 16 + r;
                int o0 = m * KPAD + kk + c2;
                int o1 = (m + 8) * KPAD + kk + c2;
                ah[mt][0] = *(uint32_t*)&Ahi[o0];
                ah[mt][1] = *(uint32_t*)&Ahi[o1];
                ah[mt][2] = *(uint32_t*)&Ahi[o0 + 8];
                ah[mt][3] = *(uint32_t*)&Ahi[o1 + 8];
            }
            #pragma unroll
            for (int nt = 0; nt < 4; nt++) {
                int n = wcol * 32 + nt * 8 + r;
                int ob = n * BW + (kk >> 1) + q;
                uint32_t bh[2], bl[2];
                bh[0] = Bhi32[ob];
                bh[1] = Bhi32[ob + 4];
                bl[0] = Blo32[ob];
                bl[1] = Blo32[ob + 4];
                #pragma unroll
                for (int mt = 0; mt < 2; mt++) {
                    mma16816(acc[mt][nt], ah[mt], bh);
                    mma16816(acc[mt][nt], ah[mt], bl);
                }
            }
        }
        __syncthreads();
    }

    // epilogue: bias -> fp16 into g_hh hop 0
    #pragma unroll
    for (int nt = 0; nt < 4; nt++) {
        int gc = wcol * 32 + nt * 8 + c2;
        float bx = __ldg(&bias[gc]), by = __ldg(&bias[gc + 1]);
        #pragma unroll
        for (int mt = 0; mt < 2; mt++) {
            int gr = mBase + wrow * 32 + mt * 16 + r;
            if (gr < NN)
                *(__half2*)(g_hh + (size_t)gr * DO + gc) =
                    __floats2half2_rn(acc[mt][nt][0] + bx, acc[mt][nt][1] + by);
            if (gr + 8 < NN)
                *(__half2*)(g_hh + (size_t)(gr + 8) * DO + gc) =
                    __floats2half2_rn(acc[mt][nt][2] + bx, acc[mt][nt][3] + by);
        }
    }
}

// ---------------- propagation hop: fp16 gather over dest-CSR -------------------
__global__ void __launch_bounds__(256) k_hop(int hop) {
    int gw = (blockIdx.x * blockDim.x + threadIdx.x) >> 5;
    if (gw >= NN) return;
    int lane = threadIdx.x & 31;
    int hf = lane >> 4, sub = lane & 15;
    const uint2* __restrict__ hprev = (const uint2*)(g_hh + (size_t)hop * NN * DO);
    uint2* __restrict__ hnew = (uint2*)(g_hh + (size_t)(hop + 1) * NN * DO);
    int start = g_off[gw], end = g_off[gw + 1];

    float ax = 0.f, ay = 0.f, az = 0.f, aw = 0.f;
    for (int base = start; base < end; base += 32) {
        int i = base + lane;
        int2 meta = make_int2(0, 0);
        if (i < end) meta = g_csr[i];
        int lim = end - base; if (lim > 32) lim = 32;
        for (int j2 = 0; j2 < lim; j2 += 2) {
            int j = (j2 + hf) & 31;
            int s = __shfl_sync(0xffffffffu, meta.x, j);
            float w = __int_as_float(__shfl_sync(0xffffffffu, meta.y, j));
            uint2 u = __ldg(&hprev[s * 16 + sub]);
            float2 f0 = __half22float2(*(__half2*)&u.x);
            float2 f1 = __half22float2(*(__half2*)&u.y);
            ax = fmaf(w, f0.x, ax); ay = fmaf(w, f0.y, ay);
            az = fmaf(w, f1.x, az); aw = fmaf(w, f1.y, aw);
        }
    }
    ax += __shfl_xor_sync(0xffffffffu, ax, 16);
    ay += __shfl_xor_sync(0xffffffffu, ay, 16);
    az += __shfl_xor_sync(0xffffffffu, az, 16);
    aw += __shfl_xor_sync(0xffffffffu, aw, 16);
    if (hf == 0) {
        float d = g_dinv[gw];
        float w = d * d;                    // self-loop
        uint2 u = __ldg(&hprev[gw * 16 + sub]);
        float2 f0 = __half22float2(*(__half2*)&u.x);
        float2 f1 = __half22float2(*(__half2*)&u.y);
        uint2 o;
        *(__half2*)&o.x = __floats2half2_rn(fmaf(w, f0.x, ax), fmaf(w, f0.y, ay));
        *(__half2*)&o.y = __floats2half2_rn(fmaf(w, f1.x, az), fmaf(w, f1.y, aw));
        hnew[gw * 16 + sub] = o;
    }
}

// ---------------- adaptive hop pooling epilogue --------------------------------
__global__ void __launch_bounds__(256) k_pool(const float* __restrict__ pw,
                                              const float* __restrict__ pb,
                                              float* __restrict__ out) {
    int gw = (blockIdx.x * blockDim.x + threadIdx.x) >> 5;
    if (gw >= NN) return;
    int lane = threadIdx.x & 31;
    float2 w2 = ((const float2*)pw)[lane];
    float bias = pb[0];
    float ox = 0.f, oy = 0.f;
    #pragma unroll
    for (int k = 0; k <= KHOPS; k++) {
        const __half2* hp = (const __half2*)(g_hh + (size_t)k * NN * DO + (size_t)gw * DO);
        float2 v = __half22float2(__ldg(&hp[lane]));
        float p = v.x * w2.x + v.y * w2.y;
        #pragma unroll
        for (int o = 16; o; o >>= 1) p += __shfl_xor_sync(0xffffffffu, p, o);
        float sc = 1.f / (1.f + expf(-(p + bias)));
        ox = fmaf(sc, v.x, ox);
        oy = fmaf(sc, v.y, oy);
    }
    ((float2*)(out + (size_t)gw * DO))[lane] = make_float2(ox, oy);
}

// ---------------- launch -------------------------------------------------------
extern "C" void kernel_launch(void* const* d_in, const int* in_sizes, int n_in,
                              void* d_out, int out_size) {
    const float* x  = (const float*)d_in[0];
    const void*  ei = d_in[1];
    const float* W1 = (const float*)d_in[2];
    const float* b1 = (const float*)d_in[3];
    const float* W2 = (const float*)d_in[4];
    const float* b2 = (const float*)d_in[5];
    const float* pw = (const float*)d_in[6];
    const float* pb = (const float*)d_in[7];
    float* out = (float*)d_out;

    k_prepW  <<<20, 256>>>(W1, W2);                                 // #0
    k_gemm1  <<<dim3(1563, 2), 256>>>(x, b1);                       // #1
    k_initdet<<<392, 256>>>((const int*)ei);                        // #2
    k_gemm2  <<<dim3(1563, 1), 128>>>(b2);                          // #3 (profiled)
    k_count  <<<(EE + 255) / 256, 256>>>(ei);                       // #4
    k_scanA  <<<NB_SCAN, 1024>>>();                                 // #5
    k_scanC  <<<NB_SCAN, 1024>>>();                                 // #6
    k_fill   <<<(EE + 255) / 256, 256>>>(ei);                       // #7

    for (int k = 0; k < KHOPS; k++)                                 // #8..17
        k_hop<<<NN / 8, 256>>>(k);

    k_pool<<<NN / 8, 256>>>(pw, pb, out);                           // #18
}